// round 5
// baseline (speedup 1.0000x reference)
#include <cuda_runtime.h>
#include <math.h>

// Problem constants (fixed shapes: B=16, C=1, T=8192, F=65, WINDOW=64)
#define T_DIM     8192
#define B_DIM     16
#define FQ        65          // rfft bins
#define NT        33          // unique t values 0..32 after even/odd + mirror
#define ROWS      69          // input rows per tile (TILE_H + 5 overlap)
#define TILE_H    64          // output rows per block
#define TRUE_LEN  (T_DIM - 5) // 8187 output rows per batch
#define XS_STRIDE 68          // padded stride for Xs (float4-aligned, bank-skewed)
#define YS_STRIDE 66          // padded stride for Y (t in 0..64)
#define C_STRIDE  68          // padded stride for coefficient table (float4-aligned, skewed)

// Packed cosine table row t: sC[t*C_STRIDE + 2i] = CE[t][i], [.. + 2i+1] = CO[t][i]
//   CE[t][i] = a_i * cos(pi*(2*i*t)/64), i=0..31, a = 1 for i==0 else 2
//   CO[t][i] = 2 * cos(pi*((2i+1)*t)/64), i=0..31
// Nyquist (freq 64) column separate: g_CE32[t] = cos(pi*t)
// irfft row (norm='forward', real input spectrum -> even signal):
//   Y[t] = E[t]+O[t],  Y[64-t] = E[t]-O[t]  (t = 0..32),  Y[t] = Y[128-t].
__device__ float g_C[NT * C_STRIDE];
__device__ float g_CE32[NT];

__global__ void init_tables_kernel() {
    int idx = blockIdx.x * blockDim.x + threadIdx.x;
    if (idx < NT * C_STRIDE) {
        int t = idx / C_STRIDE, q = idx % C_STRIDE, i = q >> 1;
        if (q >= 64) { g_C[idx] = 0.0f; }
        else if ((q & 1) == 0) {
            double a = (i == 0) ? 1.0 : 2.0;
            int m = (2 * i * t) & 127;   // phase in units of pi/64, period 128
            g_C[idx] = (float)(a * cos(M_PI * (double)m / 64.0));
        } else {
            int m = ((2 * i + 1) * t) & 127;
            g_C[idx] = (float)(2.0 * cos(M_PI * (double)m / 64.0));
        }
    }
    int idx2 = idx - NT * C_STRIDE;
    if (idx2 >= 0 && idx2 < NT) {
        g_CE32[idx2] = (idx2 & 1) ? -1.0f : 1.0f;   // cos(pi * t)
    }
}

__global__ __launch_bounds__(256, 4) void subband_kernel(
    const float* __restrict__ inp,   // [B, 1, T, FQ]
    const float* __restrict__ filt,  // [384]
    float* __restrict__ out)         // [B, 1, TRUE_LEN*64]
{
    __shared__ __align__(16) float Xs[ROWS * XS_STRIDE]; // staged input rows (padded)
    __shared__ __align__(16) float Ys[ROWS * YS_STRIDE]; // per-row irfft, t = 0..64
    __shared__ __align__(16) float sC[NT * C_STRIDE];    // interleaved CE/CO, skewed
    __shared__ float sC32[NT];
    __shared__ float sF[6 * 64];

    const int tid  = threadIdx.x;
    const int b    = blockIdx.y;
    const int base = blockIdx.x * TILE_H;

    // ---- Phase 1: stage tables + input tile into smem (coalesced gmem reads) ----
    for (int i = tid; i < NT * C_STRIDE; i += 256) sC[i] = g_C[i];
    if (tid < NT) sC32[tid] = g_CE32[tid];
    if (tid < 128) {
        sF[tid]       = filt[tid];
        sF[tid + 128] = filt[tid + 128];
        sF[tid + 256] = filt[tid + 256];
    }
    int nrows = T_DIM - base; if (nrows > ROWS) nrows = ROWS;
    const float* src = inp + ((size_t)b * T_DIM + base) * FQ;
    for (int i = tid; i < nrows * FQ; i += 256) {
        int r = i / FQ, c = i - r * FQ;
        Xs[r * XS_STRIDE + c] = src[i];
    }
    __syncthreads();

    // ---- Phase 2: per-row irfft via even/odd cosine transform ----
    // 11 t-threads (t = tt, tt+11, tt+22) x 23 row-groups (r = rg, rg+23, rg+46)
    if (tid < 253) {
        const int tt = tid % 11;
        const int rg = tid / 11;

        float aE00=0.f,aE01=0.f,aE02=0.f, aE10=0.f,aE11=0.f,aE12=0.f, aE20=0.f,aE21=0.f,aE22=0.f;
        float aO00=0.f,aO01=0.f,aO02=0.f, aO10=0.f,aO11=0.f,aO12=0.f, aO20=0.f,aO21=0.f,aO22=0.f;

        const float4* c0 = (const float4*)&sC[tt * C_STRIDE];
        const float4* c1 = (const float4*)&sC[(tt + 11) * C_STRIDE];
        const float4* c2 = (const float4*)&sC[(tt + 22) * C_STRIDE];
        const float4* x0 = (const float4*)&Xs[rg * XS_STRIDE];
        const float4* x1 = (const float4*)&Xs[(rg + 23) * XS_STRIDE];
        const float4* x2 = (const float4*)&Xs[(rg + 46) * XS_STRIDE];

        // float4 = (CE_i, CO_i, CE_{i+1}, CO_{i+1}) / (Xe_i, Xo_i, Xe_{i+1}, Xo_{i+1})
        #pragma unroll 4
        for (int i2 = 0; i2 < 16; i2++) {
            float4 cc0 = c0[i2], cc1 = c1[i2], cc2 = c2[i2];
            float4 v0 = x0[i2], v1 = x1[i2], v2 = x2[i2];
            aE00 += cc0.x * v0.x; aO00 += cc0.y * v0.y;
            aE01 += cc0.x * v1.x; aO01 += cc0.y * v1.y;
            aE02 += cc0.x * v2.x; aO02 += cc0.y * v2.y;
            aE10 += cc1.x * v0.x; aO10 += cc1.y * v0.y;
            aE11 += cc1.x * v1.x; aO11 += cc1.y * v1.y;
            aE12 += cc1.x * v2.x; aO12 += cc1.y * v2.y;
            aE20 += cc2.x * v0.x; aO20 += cc2.y * v0.y;
            aE21 += cc2.x * v1.x; aO21 += cc2.y * v1.y;
            aE22 += cc2.x * v2.x; aO22 += cc2.y * v2.y;
            aE00 += cc0.z * v0.z; aO00 += cc0.w * v0.w;
            aE01 += cc0.z * v1.z; aO01 += cc0.w * v1.w;
            aE02 += cc0.z * v2.z; aO02 += cc0.w * v2.w;
            aE10 += cc1.z * v0.z; aO10 += cc1.w * v0.w;
            aE11 += cc1.z * v1.z; aO11 += cc1.w * v1.w;
            aE12 += cc1.z * v2.z; aO12 += cc1.w * v2.w;
            aE20 += cc2.z * v0.z; aO20 += cc2.w * v0.w;
            aE21 += cc2.z * v1.z; aO21 += cc2.w * v1.w;
            aE22 += cc2.z * v2.z; aO22 += cc2.w * v2.w;
        }
        { // tail: Nyquist bin (freq 64)
            float e0 = sC32[tt], e1 = sC32[tt + 11], e2 = sC32[tt + 22];
            float xe0 = Xs[rg * XS_STRIDE + 64];
            float xe1 = Xs[(rg + 23) * XS_STRIDE + 64];
            float xe2 = Xs[(rg + 46) * XS_STRIDE + 64];
            aE00 += e0 * xe0; aE01 += e0 * xe1; aE02 += e0 * xe2;
            aE10 += e1 * xe0; aE11 += e1 * xe1; aE12 += e1 * xe2;
            aE20 += e2 * xe0; aE21 += e2 * xe1; aE22 += e2 * xe2;
        }

        // scatter Y[t] = E+O, Y[64-t] = E-O
        const int t0 = tt, t1 = tt + 11, t2 = tt + 22;
        const int r0 = rg, r1 = rg + 23, r2 = rg + 46;
        Ys[r0*YS_STRIDE + t0]      = aE00 + aO00;
        Ys[r0*YS_STRIDE + 64 - t0] = aE00 - aO00;
        Ys[r1*YS_STRIDE + t0]      = aE01 + aO01;
        Ys[r1*YS_STRIDE + 64 - t0] = aE01 - aO01;
        Ys[r2*YS_STRIDE + t0]      = aE02 + aO02;
        Ys[r2*YS_STRIDE + 64 - t0] = aE02 - aO02;
        Ys[r0*YS_STRIDE + t1]      = aE10 + aO10;
        Ys[r0*YS_STRIDE + 64 - t1] = aE10 - aO10;
        Ys[r1*YS_STRIDE + t1]      = aE11 + aO11;
        Ys[r1*YS_STRIDE + 64 - t1] = aE11 - aO11;
        Ys[r2*YS_STRIDE + t1]      = aE12 + aO12;
        Ys[r2*YS_STRIDE + 64 - t1] = aE12 - aO12;
        Ys[r0*YS_STRIDE + t2]      = aE20 + aO20;
        Ys[r0*YS_STRIDE + 64 - t2] = aE20 - aO20;
        Ys[r1*YS_STRIDE + t2]      = aE21 + aO21;
        Ys[r1*YS_STRIDE + 64 - t2] = aE21 - aO21;
        Ys[r2*YS_STRIDE + t2]      = aE22 + aO22;
        Ys[r2*YS_STRIDE + 64 - t2] = aE22 - aO22;
    }
    __syncthreads();

    // ---- Phase 3: polyphase overlap-add with rolling window ----
    // out[b,h,j] = (1/512) * (f0*Y[hl+5][j] + f1*Y[hl+4][64-j] + f2*Y[hl+3][j]
    //                        + f3*Y[hl+2][64-j] + f4*Y[hl+1][j] + f5*Y[hl][64-j])
    // Outputs at h and h+2 share 4 of 6 operands (column fixed per row parity):
    // two parity chains, 6-register sliding window, 2 new loads per output.
    const int j   = tid & 63;
    const int hg  = tid >> 6;   // 4 h-groups of 16 rows
    const int hl0 = hg * 16;
    const float f0 = sF[j],       f1 = sF[64 + j],  f2 = sF[128 + j];
    const float f3 = sF[192 + j], f4 = sF[256 + j], f5 = sF[320 + j];
    float* outb = out + (size_t)b * ((size_t)TRUE_LEN * 64);

    #pragma unroll
    for (int p = 0; p < 2; p++) {
        // chain outputs hl = hl0+p, hl0+p+2, ..., hl0+p+14
        // rows r with r ≡ p (mod 2) use col 64-j; rows r ≡ p+1 use col j
        const int colA = 64 - j;  // for rows of parity p
        const int colB = j;       // for rows of parity p^1
        int s = hl0 + p;
        float w0 = Ys[(s + 0) * YS_STRIDE + colA];
        float w1 = Ys[(s + 1) * YS_STRIDE + colB];
        float w2 = Ys[(s + 2) * YS_STRIDE + colA];
        float w3 = Ys[(s + 3) * YS_STRIDE + colB];
        float w4 = Ys[(s + 4) * YS_STRIDE + colA];
        float w5 = Ys[(s + 5) * YS_STRIDE + colB];
        #pragma unroll
        for (int q = 0; q < 8; q++) {
            float acc = f5 * w0 + f4 * w1 + f3 * w2 + f2 * w3 + f1 * w4 + f0 * w5;
            int h = base + s;
            if (h < TRUE_LEN) outb[(size_t)h * 64 + j] = acc * (1.0f / 512.0f);
            if (q < 7) {
                w0 = w2; w1 = w3; w2 = w4; w3 = w5;
                w4 = Ys[(s + 6) * YS_STRIDE + colA];
                w5 = Ys[(s + 7) * YS_STRIDE + colB];
                s += 2;
            }
        }
    }
}

extern "C" void kernel_launch(void* const* d_in, const int* in_sizes, int n_in,
                              void* d_out, int out_size) {
    const float* inp  = (const float*)d_in[0];
    const float* filt = (const float*)d_in[1];
    float* out = (float*)d_out;

    init_tables_kernel<<<10, 256>>>();                  // 2244 + 33 table entries
    dim3 grid((TRUE_LEN + TILE_H - 1) / TILE_H, B_DIM); // 128 x 16
    subband_kernel<<<grid, 256>>>(inp, filt, out);
}

// round 6
// speedup vs baseline: 1.1742x; 1.1742x over previous
#include <cuda_runtime.h>
#include <math.h>

// Problem constants (fixed shapes: B=16, C=1, T=8192, F=65, WINDOW=64)
#define T_DIM     8192
#define B_DIM     16
#define FQ        65          // rfft bins
#define NT        33          // unique t values 0..32 after even/odd + mirror
#define ROWS      69          // input rows per tile (TILE_H + 5 overlap)
#define TILE_H    64          // output rows per block
#define TRUE_LEN  (T_DIM - 5) // 8187 output rows per batch
#define XS_STRIDE 68          // padded stride for Xs (float4-aligned; X loads are broadcast)
#define YS_STRIDE 66          // padded stride for Y (t in 0..64)
#define C_STRIDE  66          // coefficient stride: bank 2*tt mod 32 -> conflict-free for 11 tt

// Packed cosine table row t: sC[t*C_STRIDE + 2i] = CE[t][i], [.. + 2i+1] = CO[t][i]
//   CE[t][i] = a_i * cos(pi*(2*i*t)/64), i=0..31, a = 1 for i==0 else 2
//   CO[t][i] = 2 * cos(pi*((2i+1)*t)/64), i=0..31
// Nyquist (freq 64) column separate: g_CE32[t] = cos(pi*t)
// irfft row (norm='forward', real input spectrum -> even signal):
//   Y[t] = E[t]+O[t],  Y[64-t] = E[t]-O[t]  (t = 0..32),  Y[t] = Y[128-t].
__device__ float g_C[NT * C_STRIDE];
__device__ float g_CE32[NT];

__global__ void init_tables_kernel() {
    int idx = blockIdx.x * blockDim.x + threadIdx.x;
    if (idx < NT * C_STRIDE) {
        int t = idx / C_STRIDE, q = idx % C_STRIDE, i = q >> 1;
        if (q >= 64) { g_C[idx] = 0.0f; }
        else if ((q & 1) == 0) {
            double a = (i == 0) ? 1.0 : 2.0;
            int m = (2 * i * t) & 127;   // phase in units of pi/64, period 128
            g_C[idx] = (float)(a * cos(M_PI * (double)m / 64.0));
        } else {
            int m = ((2 * i + 1) * t) & 127;
            g_C[idx] = (float)(2.0 * cos(M_PI * (double)m / 64.0));
        }
    }
    int idx2 = idx - NT * C_STRIDE;
    if (idx2 >= 0 && idx2 < NT) {
        g_CE32[idx2] = (idx2 & 1) ? -1.0f : 1.0f;   // cos(pi * t)
    }
}

__global__ __launch_bounds__(256, 4) void subband_kernel(
    const float* __restrict__ inp,   // [B, 1, T, FQ]
    const float* __restrict__ filt,  // [384]
    float* __restrict__ out)         // [B, 1, TRUE_LEN*64]
{
    __shared__ __align__(16) float Xs[ROWS * XS_STRIDE]; // staged input rows (padded)
    __shared__ __align__(16) float Ys[ROWS * YS_STRIDE]; // per-row irfft, t = 0..64
    __shared__ __align__(16) float sC[NT * C_STRIDE];    // interleaved CE/CO, skewed
    __shared__ float sC32[NT];
    __shared__ float sF[6 * 64];

    const int tid  = threadIdx.x;
    const int b    = blockIdx.y;
    const int base = blockIdx.x * TILE_H;

    // ---- Phase 1: stage tables + input tile into smem (coalesced gmem reads) ----
    for (int i = tid; i < NT * C_STRIDE; i += 256) sC[i] = g_C[i];
    if (tid < NT) sC32[tid] = g_CE32[tid];
    if (tid < 128) {
        sF[tid]       = filt[tid];
        sF[tid + 128] = filt[tid + 128];
        sF[tid + 256] = filt[tid + 256];
    }
    int nrows = T_DIM - base; if (nrows > ROWS) nrows = ROWS;
    const float* src = inp + ((size_t)b * T_DIM + base) * FQ;
    for (int i = tid; i < nrows * FQ; i += 256) {
        int r = i / FQ, c = i - r * FQ;
        Xs[r * XS_STRIDE + c] = src[i];
    }
    __syncthreads();

    // ---- Phase 2: per-row irfft via even/odd cosine transform ----
    // 11 t-threads (t = tt, tt+11, tt+22) x 23 row-groups (r = rg, rg+23, rg+46)
    if (tid < 253) {
        const int tt = tid % 11;
        const int rg = tid / 11;

        float aE00=0.f,aE01=0.f,aE02=0.f, aE10=0.f,aE11=0.f,aE12=0.f, aE20=0.f,aE21=0.f,aE22=0.f;
        float aO00=0.f,aO01=0.f,aO02=0.f, aO10=0.f,aO11=0.f,aO12=0.f, aO20=0.f,aO21=0.f,aO22=0.f;

        const float2* c0 = (const float2*)&sC[tt * C_STRIDE];          // conflict-free
        const float2* c1 = (const float2*)&sC[(tt + 11) * C_STRIDE];
        const float2* c2 = (const float2*)&sC[(tt + 22) * C_STRIDE];
        const float4* x0 = (const float4*)&Xs[rg * XS_STRIDE];         // broadcast (3 addrs)
        const float4* x1 = (const float4*)&Xs[(rg + 23) * XS_STRIDE];
        const float4* x2 = (const float4*)&Xs[(rg + 46) * XS_STRIDE];

        // Per iteration: 2 i-steps. coef: 6x LDS.64 (float2), X: 3x LDS.128 (float4).
        #pragma unroll 4
        for (int i2 = 0; i2 < 16; i2++) {
            float4 v0 = x0[i2], v1 = x1[i2], v2 = x2[i2];
            float2 a0 = c0[2*i2], b0 = c0[2*i2+1];
            float2 a1 = c1[2*i2], b1 = c1[2*i2+1];
            float2 a2 = c2[2*i2], b2 = c2[2*i2+1];
            aE00 += a0.x * v0.x; aO00 += a0.y * v0.y;
            aE01 += a0.x * v1.x; aO01 += a0.y * v1.y;
            aE02 += a0.x * v2.x; aO02 += a0.y * v2.y;
            aE10 += a1.x * v0.x; aO10 += a1.y * v0.y;
            aE11 += a1.x * v1.x; aO11 += a1.y * v1.y;
            aE12 += a1.x * v2.x; aO12 += a1.y * v2.y;
            aE20 += a2.x * v0.x; aO20 += a2.y * v0.y;
            aE21 += a2.x * v1.x; aO21 += a2.y * v1.y;
            aE22 += a2.x * v2.x; aO22 += a2.y * v2.y;
            aE00 += b0.x * v0.z; aO00 += b0.y * v0.w;
            aE01 += b0.x * v1.z; aO01 += b0.y * v1.w;
            aE02 += b0.x * v2.z; aO02 += b0.y * v2.w;
            aE10 += b1.x * v0.z; aO10 += b1.y * v0.w;
            aE11 += b1.x * v1.z; aO11 += b1.y * v1.w;
            aE12 += b1.x * v2.z; aO12 += b1.y * v2.w;
            aE20 += b2.x * v0.z; aO20 += b2.y * v0.w;
            aE21 += b2.x * v1.z; aO21 += b2.y * v1.w;
            aE22 += b2.x * v2.z; aO22 += b2.y * v2.w;
        }
        { // tail: Nyquist bin (freq 64)
            float e0 = sC32[tt], e1 = sC32[tt + 11], e2 = sC32[tt + 22];
            float xe0 = Xs[rg * XS_STRIDE + 64];
            float xe1 = Xs[(rg + 23) * XS_STRIDE + 64];
            float xe2 = Xs[(rg + 46) * XS_STRIDE + 64];
            aE00 += e0 * xe0; aE01 += e0 * xe1; aE02 += e0 * xe2;
            aE10 += e1 * xe0; aE11 += e1 * xe1; aE12 += e1 * xe2;
            aE20 += e2 * xe0; aE21 += e2 * xe1; aE22 += e2 * xe2;
        }

        // scatter Y[t] = E+O, Y[64-t] = E-O
        const int t0 = tt, t1 = tt + 11, t2 = tt + 22;
        const int r0 = rg, r1 = rg + 23, r2 = rg + 46;
        Ys[r0*YS_STRIDE + t0]      = aE00 + aO00;
        Ys[r0*YS_STRIDE + 64 - t0] = aE00 - aO00;
        Ys[r1*YS_STRIDE + t0]      = aE01 + aO01;
        Ys[r1*YS_STRIDE + 64 - t0] = aE01 - aO01;
        Ys[r2*YS_STRIDE + t0]      = aE02 + aO02;
        Ys[r2*YS_STRIDE + 64 - t0] = aE02 - aO02;
        Ys[r0*YS_STRIDE + t1]      = aE10 + aO10;
        Ys[r0*YS_STRIDE + 64 - t1] = aE10 - aO10;
        Ys[r1*YS_STRIDE + t1]      = aE11 + aO11;
        Ys[r1*YS_STRIDE + 64 - t1] = aE11 - aO11;
        Ys[r2*YS_STRIDE + t1]      = aE12 + aO12;
        Ys[r2*YS_STRIDE + 64 - t1] = aE12 - aO12;
        Ys[r0*YS_STRIDE + t2]      = aE20 + aO20;
        Ys[r0*YS_STRIDE + 64 - t2] = aE20 - aO20;
        Ys[r1*YS_STRIDE + t2]      = aE21 + aO21;
        Ys[r1*YS_STRIDE + 64 - t2] = aE21 - aO21;
        Ys[r2*YS_STRIDE + t2]      = aE22 + aO22;
        Ys[r2*YS_STRIDE + 64 - t2] = aE22 - aO22;
    }
    __syncthreads();

    // ---- Phase 3: polyphase overlap-add with rolling window ----
    // out[b,h,j] = (1/512) * (f0*Y[hl+5][j] + f1*Y[hl+4][64-j] + f2*Y[hl+3][j]
    //                        + f3*Y[hl+2][64-j] + f4*Y[hl+1][j] + f5*Y[hl][64-j])
    // Outputs at h and h+2 share 4 of 6 operands: two parity chains,
    // 6-register sliding window, 2 new loads per output.
    const int j   = tid & 63;
    const int hg  = tid >> 6;   // 4 h-groups of 16 rows
    const int hl0 = hg * 16;
    const float f0 = sF[j],       f1 = sF[64 + j],  f2 = sF[128 + j];
    const float f3 = sF[192 + j], f4 = sF[256 + j], f5 = sF[320 + j];
    float* outb = out + (size_t)b * ((size_t)TRUE_LEN * 64);

    #pragma unroll
    for (int p = 0; p < 2; p++) {
        const int colA = 64 - j;  // for rows of parity p
        const int colB = j;       // for rows of parity p^1
        int s = hl0 + p;
        float w0 = Ys[(s + 0) * YS_STRIDE + colA];
        float w1 = Ys[(s + 1) * YS_STRIDE + colB];
        float w2 = Ys[(s + 2) * YS_STRIDE + colA];
        float w3 = Ys[(s + 3) * YS_STRIDE + colB];
        float w4 = Ys[(s + 4) * YS_STRIDE + colA];
        float w5 = Ys[(s + 5) * YS_STRIDE + colB];
        #pragma unroll
        for (int q = 0; q < 8; q++) {
            float acc = f5 * w0 + f4 * w1 + f3 * w2 + f2 * w3 + f1 * w4 + f0 * w5;
            int h = base + s;
            if (h < TRUE_LEN) outb[(size_t)h * 64 + j] = acc * (1.0f / 512.0f);
            if (q < 7) {
                w0 = w2; w1 = w3; w2 = w4; w3 = w5;
                w4 = Ys[(s + 6) * YS_STRIDE + colA];
                w5 = Ys[(s + 7) * YS_STRIDE + colB];
                s += 2;
            }
        }
    }
}

extern "C" void kernel_launch(void* const* d_in, const int* in_sizes, int n_in,
                              void* d_out, int out_size) {
    const float* inp  = (const float*)d_in[0];
    const float* filt = (const float*)d_in[1];
    float* out = (float*)d_out;

    init_tables_kernel<<<10, 256>>>();                  // table entries
    dim3 grid((TRUE_LEN + TILE_H - 1) / TILE_H, B_DIM); // 128 x 16
    subband_kernel<<<grid, 256>>>(inp, filt, out);
}

// round 7
// speedup vs baseline: 1.2270x; 1.0450x over previous
#include <cuda_runtime.h>
#include <math.h>

// Problem constants (fixed shapes: B=16, C=1, T=8192, F=65, WINDOW=64)
#define T_DIM     8192
#define B_DIM     16
#define FQ        65          // rfft bins
#define NT        33          // unique t values 0..32 after even/odd + mirror
#define ROWS      69          // input rows per tile (TILE_H + 5 overlap)
#define TILE_H    64          // output rows per block
#define TRUE_LEN  (T_DIM - 5) // 8187 output rows per batch
#define XS_STRIDE 68          // padded stride for Xs (float4-aligned; X loads are broadcast)
#define YS_STRIDE 72          // scatter banks 8*rg+tt -> near conflict-free; even for alignment
#define C_STRIDE  66          // coefficient stride: bank 2*tt mod 32 -> conflict-free for 11 tt

typedef unsigned long long u64;

// fused dual-FMA: d.lo = a.lo*b.lo + c.lo ; d.hi = a.hi*b.hi + c.hi  (full fp32 each lane)
#define FMA_F32X2(d, a, b, c) \
    asm("fma.rn.f32x2 %0, %1, %2, %3;" : "=l"(d) : "l"(a), "l"(b), "l"(c))
#define UNPACK_F32X2(lo, hi, in) \
    asm("mov.b64 {%0, %1}, %2;" : "=f"(lo), "=f"(hi) : "l"(in))

// Packed cosine table row t: sC[t*C_STRIDE + 2i] = CE[t][i], [.. + 2i+1] = CO[t][i]
//   CE[t][i] = a_i * cos(pi*(2*i*t)/64), i=0..31, a = 1 for i==0 else 2
//   CO[t][i] = 2 * cos(pi*((2i+1)*t)/64), i=0..31
// Nyquist (freq 64) column separate: g_CE32[t] = cos(pi*t)
// irfft row (norm='forward', real input spectrum -> even signal):
//   Y[t] = E[t]+O[t],  Y[64-t] = E[t]-O[t]  (t = 0..32),  Y[t] = Y[128-t].
__device__ float g_C[NT * C_STRIDE];
__device__ float g_CE32[NT];

__global__ void init_tables_kernel() {
    int idx = blockIdx.x * blockDim.x + threadIdx.x;
    if (idx < NT * C_STRIDE) {
        int t = idx / C_STRIDE, q = idx % C_STRIDE, i = q >> 1;
        if (q >= 64) { g_C[idx] = 0.0f; }
        else if ((q & 1) == 0) {
            double a = (i == 0) ? 1.0 : 2.0;
            int m = (2 * i * t) & 127;   // phase in units of pi/64, period 128
            g_C[idx] = (float)(a * cos(M_PI * (double)m / 64.0));
        } else {
            int m = ((2 * i + 1) * t) & 127;
            g_C[idx] = (float)(2.0 * cos(M_PI * (double)m / 64.0));
        }
    }
    int idx2 = idx - NT * C_STRIDE;
    if (idx2 >= 0 && idx2 < NT) {
        g_CE32[idx2] = (idx2 & 1) ? -1.0f : 1.0f;   // cos(pi * t)
    }
}

__global__ __launch_bounds__(256, 4) void subband_kernel(
    const float* __restrict__ inp,   // [B, 1, T, FQ]
    const float* __restrict__ filt,  // [384]
    float* __restrict__ out)         // [B, 1, TRUE_LEN*64]
{
    __shared__ __align__(16) float Xs[ROWS * XS_STRIDE]; // staged input rows (padded)
    __shared__ __align__(16) float Ys[ROWS * YS_STRIDE]; // per-row irfft, t = 0..64
    __shared__ __align__(16) float sC[NT * C_STRIDE];    // interleaved CE/CO, skewed
    __shared__ float sC32[NT];
    __shared__ float sF[6 * 64];

    const int tid  = threadIdx.x;
    const int b    = blockIdx.y;
    const int base = blockIdx.x * TILE_H;

    // ---- Phase 1: stage tables + input tile into smem (coalesced gmem reads) ----
    for (int i = tid; i < NT * C_STRIDE; i += 256) sC[i] = g_C[i];
    if (tid < NT) sC32[tid] = g_CE32[tid];
    if (tid < 128) {
        sF[tid]       = filt[tid];
        sF[tid + 128] = filt[tid + 128];
        sF[tid + 256] = filt[tid + 256];
    }
    int nrows = T_DIM - base; if (nrows > ROWS) nrows = ROWS;
    const float* src = inp + ((size_t)b * T_DIM + base) * FQ;
    for (int i = tid; i < nrows * FQ; i += 256) {
        int r = i / FQ, c = i - r * FQ;
        Xs[r * XS_STRIDE + c] = src[i];
    }
    __syncthreads();

    // ---- Phase 2: per-row irfft via even/odd cosine transform (packed f32x2) ----
    // 11 t-threads (t = tt, tt+11, tt+22) x 23 row-groups (r = rg, rg+23, rg+46)
    if (tid < 253) {
        const int tt = tid % 11;
        const int rg = tid / 11;

        // accumulators: lo = E, hi = O
        u64 a00 = 0ull, a01 = 0ull, a02 = 0ull;
        u64 a10 = 0ull, a11 = 0ull, a12 = 0ull;
        u64 a20 = 0ull, a21 = 0ull, a22 = 0ull;

        const u64* c0 = (const u64*)&sC[tt * C_STRIDE];          // conflict-free
        const u64* c1 = (const u64*)&sC[(tt + 11) * C_STRIDE];
        const u64* c2 = (const u64*)&sC[(tt + 22) * C_STRIDE];
        const ulonglong2* x0 = (const ulonglong2*)&Xs[rg * XS_STRIDE];  // broadcast
        const ulonglong2* x1 = (const ulonglong2*)&Xs[(rg + 23) * XS_STRIDE];
        const ulonglong2* x2 = (const ulonglong2*)&Xs[(rg + 46) * XS_STRIDE];

        // Per iteration: 2 i-steps. 18 FFMA2 + 6 LDS.64 (coef) + 3 LDS.128 (X).
        #pragma unroll 4
        for (int i2 = 0; i2 < 16; i2++) {
            ulonglong2 v0 = x0[i2], v1 = x1[i2], v2 = x2[i2];
            u64 cA0 = c0[2*i2], cB0 = c0[2*i2+1];
            u64 cA1 = c1[2*i2], cB1 = c1[2*i2+1];
            u64 cA2 = c2[2*i2], cB2 = c2[2*i2+1];
            FMA_F32X2(a00, cA0, v0.x, a00);  FMA_F32X2(a00, cB0, v0.y, a00);
            FMA_F32X2(a01, cA0, v1.x, a01);  FMA_F32X2(a01, cB0, v1.y, a01);
            FMA_F32X2(a02, cA0, v2.x, a02);  FMA_F32X2(a02, cB0, v2.y, a02);
            FMA_F32X2(a10, cA1, v0.x, a10);  FMA_F32X2(a10, cB1, v0.y, a10);
            FMA_F32X2(a11, cA1, v1.x, a11);  FMA_F32X2(a11, cB1, v1.y, a11);
            FMA_F32X2(a12, cA1, v2.x, a12);  FMA_F32X2(a12, cB1, v2.y, a12);
            FMA_F32X2(a20, cA2, v0.x, a20);  FMA_F32X2(a20, cB2, v0.y, a20);
            FMA_F32X2(a21, cA2, v1.x, a21);  FMA_F32X2(a21, cB2, v1.y, a21);
            FMA_F32X2(a22, cA2, v2.x, a22);  FMA_F32X2(a22, cB2, v2.y, a22);
        }

        // unpack E/O
        float E00,O00,E01,O01,E02,O02,E10,O10,E11,O11,E12,O12,E20,O20,E21,O21,E22,O22;
        UNPACK_F32X2(E00, O00, a00); UNPACK_F32X2(E01, O01, a01); UNPACK_F32X2(E02, O02, a02);
        UNPACK_F32X2(E10, O10, a10); UNPACK_F32X2(E11, O11, a11); UNPACK_F32X2(E12, O12, a12);
        UNPACK_F32X2(E20, O20, a20); UNPACK_F32X2(E21, O21, a21); UNPACK_F32X2(E22, O22, a22);

        { // tail: Nyquist bin (freq 64) contributes to E only
            float e0 = sC32[tt], e1 = sC32[tt + 11], e2 = sC32[tt + 22];
            float xe0 = Xs[rg * XS_STRIDE + 64];
            float xe1 = Xs[(rg + 23) * XS_STRIDE + 64];
            float xe2 = Xs[(rg + 46) * XS_STRIDE + 64];
            E00 += e0 * xe0; E01 += e0 * xe1; E02 += e0 * xe2;
            E10 += e1 * xe0; E11 += e1 * xe1; E12 += e1 * xe2;
            E20 += e2 * xe0; E21 += e2 * xe1; E22 += e2 * xe2;
        }

        // scatter Y[t] = E+O, Y[64-t] = E-O
        const int t0 = tt, t1 = tt + 11, t2 = tt + 22;
        const int r0 = rg, r1 = rg + 23, r2 = rg + 46;
        Ys[r0*YS_STRIDE + t0]      = E00 + O00;
        Ys[r0*YS_STRIDE + 64 - t0] = E00 - O00;
        Ys[r1*YS_STRIDE + t0]      = E01 + O01;
        Ys[r1*YS_STRIDE + 64 - t0] = E01 - O01;
        Ys[r2*YS_STRIDE + t0]      = E02 + O02;
        Ys[r2*YS_STRIDE + 64 - t0] = E02 - O02;
        Ys[r0*YS_STRIDE + t1]      = E10 + O10;
        Ys[r0*YS_STRIDE + 64 - t1] = E10 - O10;
        Ys[r1*YS_STRIDE + t1]      = E11 + O11;
        Ys[r1*YS_STRIDE + 64 - t1] = E11 - O11;
        Ys[r2*YS_STRIDE + t1]      = E12 + O12;
        Ys[r2*YS_STRIDE + 64 - t1] = E12 - O12;
        Ys[r0*YS_STRIDE + t2]      = E20 + O20;
        Ys[r0*YS_STRIDE + 64 - t2] = E20 - O20;
        Ys[r1*YS_STRIDE + t2]      = E21 + O21;
        Ys[r1*YS_STRIDE + 64 - t2] = E21 - O21;
        Ys[r2*YS_STRIDE + t2]      = E22 + O22;
        Ys[r2*YS_STRIDE + 64 - t2] = E22 - O22;
    }
    __syncthreads();

    // ---- Phase 3: polyphase overlap-add with rolling window ----
    // out[b,h,j] = (1/512) * (f0*Y[hl+5][j] + f1*Y[hl+4][64-j] + f2*Y[hl+3][j]
    //                        + f3*Y[hl+2][64-j] + f4*Y[hl+1][j] + f5*Y[hl][64-j])
    const int j   = tid & 63;
    const int hg  = tid >> 6;   // 4 h-groups of 16 rows
    const int hl0 = hg * 16;
    const float f0 = sF[j],       f1 = sF[64 + j],  f2 = sF[128 + j];
    const float f3 = sF[192 + j], f4 = sF[256 + j], f5 = sF[320 + j];
    float* outb = out + (size_t)b * ((size_t)TRUE_LEN * 64);

    #pragma unroll
    for (int p = 0; p < 2; p++) {
        const int colA = 64 - j;  // for rows of parity p
        const int colB = j;       // for rows of parity p^1
        int s = hl0 + p;
        float w0 = Ys[(s + 0) * YS_STRIDE + colA];
        float w1 = Ys[(s + 1) * YS_STRIDE + colB];
        float w2 = Ys[(s + 2) * YS_STRIDE + colA];
        float w3 = Ys[(s + 3) * YS_STRIDE + colB];
        float w4 = Ys[(s + 4) * YS_STRIDE + colA];
        float w5 = Ys[(s + 5) * YS_STRIDE + colB];
        #pragma unroll
        for (int q = 0; q < 8; q++) {
            float acc = f5 * w0 + f4 * w1 + f3 * w2 + f2 * w3 + f1 * w4 + f0 * w5;
            int h = base + s;
            if (h < TRUE_LEN) outb[(size_t)h * 64 + j] = acc * (1.0f / 512.0f);
            if (q < 7) {
                w0 = w2; w1 = w3; w2 = w4; w3 = w5;
                w4 = Ys[(s + 6) * YS_STRIDE + colA];
                w5 = Ys[(s + 7) * YS_STRIDE + colB];
                s += 2;
            }
        }
    }
}

extern "C" void kernel_launch(void* const* d_in, const int* in_sizes, int n_in,
                              void* d_out, int out_size) {
    const float* inp  = (const float*)d_in[0];
    const float* filt = (const float*)d_in[1];
    float* out = (float*)d_out;

    init_tables_kernel<<<10, 256>>>();                  // table entries
    dim3 grid((TRUE_LEN + TILE_H - 1) / TILE_H, B_DIM); // 128 x 16
    subband_kernel<<<grid, 256>>>(inp, filt, out);
}

// round 9
// speedup vs baseline: 1.4172x; 1.1550x over previous
#include <cuda_runtime.h>
#include <math.h>

// Problem constants (fixed shapes: B=16, C=1, T=8192, F=65, WINDOW=64)
#define T_DIM     8192
#define B_DIM     16
#define FQ        65          // rfft bins
#define ROWS      69          // real input rows per tile (TILE_H + 5 overlap)
#define ROWS_PAD  70          // padded rows (14 rg-groups x 5)
#define TILE_H    64          // output rows per block
#define TRUE_LEN  (T_DIM - 5) // 8187 output rows per batch
#define XS_STRIDE 68          // Xs row stride
#define YS_STRIDE 68          // Ys row stride
#define XF_STRIDE 36          // folded-X row stride (16B aligned: 144 B)
#define CS        34          // coef row stride (33 values + pad)
#define NTT       17          // t-groups: t in {tt, tt+16}
#define NRG       14          // row-groups of 5 consecutive rows

typedef unsigned long long u64;

// fused dual-FMA: d.lo = a.lo*b.lo + c.lo ; d.hi = a.hi*b.hi + c.hi
#define FMA_F32X2(d, a, b, c) \
    asm("fma.rn.f32x2 %0, %1, %2, %3;" : "=l"(d) : "l"(a), "l"(b), "l"(c))
#define UNPACK_F32X2(lo, hi, in) \
    asm("mov.b64 {%0, %1}, %2;" : "=f"(lo), "=f"(hi) : "l"(in))

// Folded cosine table, row t (t = 0..32), interleaved pairs:
//   g_Cf[t*CS + 2k]   = CEf[t][k] = (k==0 ? 1 : 2) * cos(2*k*t*pi/64),  k=0..15
//   g_Cf[t*CS + 2k+1] = COf[t][k] = 2 * cos((2k+1)*t*pi/64),            k=0..15
//   g_Cf[t*CS + 32]   = c16[t]    = 2 * cos(pi*t/2)  (center term, freq 32)
// Consumed with folded spectra (s = +1 for even t, -1 for odd t):
//   XeF[k] = Xe[k] + s*Xe[32-k]   (k=0 pairs DC with Nyquist)
//   XoF[k] = Xo[k] + s*Xo[31-k]
//   E[t] = sum_k CEf*XeF + c16[t]*Xe[16],  O[t] = sum_k COf*XoF
//   Y[t] = E+O, Y[64-t] = E-O  (irfft of real spectrum, norm='forward')
__device__ float g_Cf[33 * CS];

__global__ void init_tables_kernel() {
    int idx = blockIdx.x * blockDim.x + threadIdx.x;
    if (idx < 33 * CS) {
        int t = idx / CS, q = idx % CS;
        float v = 0.0f;
        if (q < 32) {
            int k = q >> 1;
            if ((q & 1) == 0) {
                double a = (k == 0) ? 1.0 : 2.0;
                int m = (2 * k * t) & 127;           // phase units of pi/64
                v = (float)(a * cos(M_PI * (double)m / 64.0));
            } else {
                int m = ((2 * k + 1) * t) & 127;
                v = (float)(2.0 * cos(M_PI * (double)m / 64.0));
            }
        } else if (q == 32) {
            int m4 = t & 3;                          // 2*cos(pi*t/2)
            v = (m4 == 0) ? 2.0f : (m4 == 2) ? -2.0f : 0.0f;
        }
        g_Cf[idx] = v;
    }
}

__global__ __launch_bounds__(256, 4) void subband_kernel(
    const float* __restrict__ inp,   // [B, 1, T, FQ]
    const float* __restrict__ filt,  // [384]
    float* __restrict__ out)         // [B, 1, TRUE_LEN*64]
{
    // Xs (phase 1/fold) and Ys (phase 2/3) alias: Xs dead once fold completes.
    __shared__ __align__(16) float pool[ROWS_PAD * XS_STRIDE];     // 70*68
    __shared__ __align__(16) float sXF[2 * ROWS_PAD * XF_STRIDE];  // folded, both parities
    __shared__ __align__(16) float sC[33 * CS];
    __shared__ float sXC[ROWS_PAD];                                // Xe[16] = X[freq 32]
    __shared__ float sF[6 * 64];

    float* Xs = pool;
    float* Ys = pool;

    const int tid  = threadIdx.x;
    const int b    = blockIdx.y;
    const int base = blockIdx.x * TILE_H;

    // ---- Phase 1: stage tables + input tile (coalesced gmem reads) ----
    for (int i = tid; i < 33 * CS; i += 256) sC[i] = g_Cf[i];
    if (tid < 128) {
        sF[tid]       = filt[tid];
        sF[tid + 128] = filt[tid + 128];
        sF[tid + 256] = filt[tid + 256];
    }
    int nrows = T_DIM - base; if (nrows > ROWS) nrows = ROWS;
    const float* src = inp + ((size_t)b * T_DIM + base) * FQ;
    for (int i = tid; i < nrows * FQ; i += 256) {
        int r = i / FQ, c = i - r * FQ;
        Xs[r * XS_STRIDE + c] = src[i];
    }
    __syncthreads();

    // ---- Phase 1.5: parity folding of the spectrum ----
    // (rows >= nrows hold garbage; their results are never stored — benign)
    for (int item = tid; item < ROWS_PAD * 16; item += 256) {
        int r = item >> 4, k = item & 15;
        const float* x = &Xs[r * XS_STRIDE];
        float xeA = x[2 * k],     xeB = x[64 - 2 * k];   // Xe[k], Xe[32-k]
        float xoA = x[2 * k + 1], xoB = x[63 - 2 * k];   // Xo[k], Xo[31-k]
        float* f0 = &sXF[r * XF_STRIDE + 2 * k];
        float* f1 = f0 + ROWS_PAD * XF_STRIDE;
        f0[0] = xeA + xeB;  f0[1] = xoA + xoB;           // even-t fold
        f1[0] = xeA - xeB;  f1[1] = xoA - xoB;           // odd-t fold
        if (k == 0) sXC[r] = x[32];                      // Xe[16] (freq 32)
    }
    __syncthreads();

    // ---- Phase 2: folded cosine transform (packed f32x2: lo=E, hi=O) ----
    // tt in [0,17): t0 = tt, t1 = tt+16 (same parity). rg in [0,14): rows rg*5..rg*5+4.
    if (tid < NTT * NRG) {
        const int tt = tid % NTT;
        const int rg = tid / NTT;
        const int r0 = rg * 5;

        u64 a0q0=0ull,a0q1=0ull,a0q2=0ull,a0q3=0ull,a0q4=0ull;   // t0 accumulators
        u64 a1q0=0ull,a1q1=0ull,a1q2=0ull,a1q3=0ull,a1q4=0ull;   // t1 accumulators

        const u64* cT0 = (const u64*)&sC[tt * CS];
        const u64* cT1 = (const u64*)&sC[(tt + 16) * CS];
        const float* xfb = &sXF[(tt & 1) * (ROWS_PAD * XF_STRIDE) + r0 * XF_STRIDE];

        #pragma unroll
        for (int i2 = 0; i2 < 8; i2++) {                 // 2 k-steps per iter
            u64 cA0 = cT0[2*i2], cB0 = cT0[2*i2+1];
            u64 cA1 = cT1[2*i2], cB1 = cT1[2*i2+1];
            ulonglong2 v0 = ((const ulonglong2*)(xfb + 0 * XF_STRIDE))[i2];
            ulonglong2 v1 = ((const ulonglong2*)(xfb + 1 * XF_STRIDE))[i2];
            ulonglong2 v2 = ((const ulonglong2*)(xfb + 2 * XF_STRIDE))[i2];
            ulonglong2 v3 = ((const ulonglong2*)(xfb + 3 * XF_STRIDE))[i2];
            ulonglong2 v4 = ((const ulonglong2*)(xfb + 4 * XF_STRIDE))[i2];
            FMA_F32X2(a0q0, cA0, v0.x, a0q0);  FMA_F32X2(a0q0, cB0, v0.y, a0q0);
            FMA_F32X2(a1q0, cA1, v0.x, a1q0);  FMA_F32X2(a1q0, cB1, v0.y, a1q0);
            FMA_F32X2(a0q1, cA0, v1.x, a0q1);  FMA_F32X2(a0q1, cB0, v1.y, a0q1);
            FMA_F32X2(a1q1, cA1, v1.x, a1q1);  FMA_F32X2(a1q1, cB1, v1.y, a1q1);
            FMA_F32X2(a0q2, cA0, v2.x, a0q2);  FMA_F32X2(a0q2, cB0, v2.y, a0q2);
            FMA_F32X2(a1q2, cA1, v2.x, a1q2);  FMA_F32X2(a1q2, cB1, v2.y, a1q2);
            FMA_F32X2(a0q3, cA0, v3.x, a0q3);  FMA_F32X2(a0q3, cB0, v3.y, a0q3);
            FMA_F32X2(a1q3, cA1, v3.x, a1q3);  FMA_F32X2(a1q3, cB1, v3.y, a1q3);
            FMA_F32X2(a0q4, cA0, v4.x, a0q4);  FMA_F32X2(a0q4, cB0, v4.y, a0q4);
            FMA_F32X2(a1q4, cA1, v4.x, a1q4);  FMA_F32X2(a1q4, cB1, v4.y, a1q4);
        }

        const float c16a = sC[tt * CS + 32];
        const float c16b = sC[(tt + 16) * CS + 32];
        const int t0 = tt, t1 = tt + 16;

        u64 accs[10] = {a0q0,a1q0,a0q1,a1q1,a0q2,a1q2,a0q3,a1q3,a0q4,a1q4};
        #pragma unroll
        for (int q = 0; q < 5; q++) {
            float E0, O0, E1, O1;
            UNPACK_F32X2(E0, O0, accs[2*q]);
            UNPACK_F32X2(E1, O1, accs[2*q+1]);
            float xc = sXC[r0 + q];
            E0 += c16a * xc;                    // center term (freq 32)
            E1 += c16b * xc;
            float* yr = &Ys[(r0 + q) * YS_STRIDE];
            yr[t0]      = E0 + O0;
            yr[64 - t0] = E0 - O0;
            yr[t1]      = E1 + O1;              // t=16 written twice (tt=0 & tt=16),
            yr[64 - t1] = E1 - O1;              // identical values — benign
        }
    }
    __syncthreads();

    // ---- Phase 3: polyphase overlap-add with rolling window ----
    // out[b,h,j] = (1/512) * (f0*Y[hl+5][j] + f1*Y[hl+4][64-j] + f2*Y[hl+3][j]
    //                        + f3*Y[hl+2][64-j] + f4*Y[hl+1][j] + f5*Y[hl][64-j])
    const int j   = tid & 63;
    const int hg  = tid >> 6;   // 4 h-groups of 16 rows
    const int hl0 = hg * 16;
    const float f0 = sF[j],       f1 = sF[64 + j],  f2 = sF[128 + j];
    const float f3 = sF[192 + j], f4 = sF[256 + j], f5 = sF[320 + j];
    float* outb = out + (size_t)b * ((size_t)TRUE_LEN * 64);

    #pragma unroll
    for (int p = 0; p < 2; p++) {
        const int colA = 64 - j;  // rows of parity p
        const int colB = j;       // rows of parity p^1
        int s = hl0 + p;
        float w0 = Ys[(s + 0) * YS_STRIDE + colA];
        float w1 = Ys[(s + 1) * YS_STRIDE + colB];
        float w2 = Ys[(s + 2) * YS_STRIDE + colA];
        float w3 = Ys[(s + 3) * YS_STRIDE + colB];
        float w4 = Ys[(s + 4) * YS_STRIDE + colA];
        float w5 = Ys[(s + 5) * YS_STRIDE + colB];
        #pragma unroll
        for (int q = 0; q < 8; q++) {
            float acc = f5 * w0 + f4 * w1 + f3 * w2 + f2 * w3 + f1 * w4 + f0 * w5;
            int h = base + s;
            if (h < TRUE_LEN) outb[(size_t)h * 64 + j] = acc * (1.0f / 512.0f);
            if (q < 7) {
                w0 = w2; w1 = w3; w2 = w4; w3 = w5;
                w4 = Ys[(s + 6) * YS_STRIDE + colA];
                w5 = Ys[(s + 7) * YS_STRIDE + colB];
                s += 2;
            }
        }
    }
}

extern "C" void kernel_launch(void* const* d_in, const int* in_sizes, int n_in,
                              void* d_out, int out_size) {
    const float* inp  = (const float*)d_in[0];
    const float* filt = (const float*)d_in[1];
    float* out = (float*)d_out;

    init_tables_kernel<<<5, 256>>>();                   // 33*34 table entries
    dim3 grid((TRUE_LEN + TILE_H - 1) / TILE_H, B_DIM); // 128 x 16
    subband_kernel<<<grid, 256>>>(inp, filt, out);
}

// round 10
// speedup vs baseline: 1.4722x; 1.0388x over previous
#include <cuda_runtime.h>
#include <math.h>

// Problem constants (fixed shapes: B=16, C=1, T=8192, F=65, WINDOW=64)
#define T_DIM     8192
#define B_DIM     16
#define FQ        65          // rfft bins
#define ROWS      69          // real input rows per tile (TILE_H + 5 overlap)
#define ROWS_PAD  70          // padded rows (14 rg-groups x 5)
#define TILE_H    64          // output rows per block
#define TRUE_LEN  (T_DIM - 5) // 8187 output rows per batch
#define YS_STRIDE 68          // (E,O)-pair row stride in floats (34 float2)
#define XF_STRIDE 36          // folded-X row stride (16B aligned: 144 B)
#define CS        34          // coef row stride (33 values + pad)
#define NTT       17          // t-groups: t in {tt, tt+16}
#define NRG       14          // row-groups of 5 consecutive rows

typedef unsigned long long u64;

// fused dual-FMA: d.lo = a.lo*b.lo + c.lo ; d.hi = a.hi*b.hi + c.hi
#define FMA_F32X2(d, a, b, c) \
    asm("fma.rn.f32x2 %0, %1, %2, %3;" : "=l"(d) : "l"(a), "l"(b), "l"(c))
#define UNPACK_F32X2(lo, hi, in) \
    asm("mov.b64 {%0, %1}, %2;" : "=f"(lo), "=f"(hi) : "l"(in))

// Folded cosine table, row t (t = 0..32), interleaved pairs:
//   g_Cf[t*CS + 2k]   = CEf[t][k] = (k==0 ? 1 : 2) * cos(2*k*t*pi/64),  k=0..15
//   g_Cf[t*CS + 2k+1] = COf[t][k] = 2 * cos((2k+1)*t*pi/64),            k=0..15
//   g_Cf[t*CS + 32]   = c16[t]    = 2 * cos(pi*t/2)  (center term, freq 32)
// Consumed with folded spectra (s = +1 for even t, -1 for odd t):
//   XeF[k] = Xe[k] + s*Xe[32-k]   (k=0 pairs DC with Nyquist)
//   XoF[k] = Xo[k] + s*Xo[31-k]
//   E[t] = sum_k CEf*XeF + c16[t]*Xe[16],  O[t] = sum_k COf*XoF
//   Y[t] = E+O, Y[64-t] = E-O  (irfft of real spectrum, norm='forward')
__device__ float g_Cf[33 * CS];

__global__ void init_tables_kernel() {
    int idx = blockIdx.x * blockDim.x + threadIdx.x;
    if (idx < 33 * CS) {
        int t = idx / CS, q = idx % CS;
        float v = 0.0f;
        if (q < 32) {
            int k = q >> 1;
            if ((q & 1) == 0) {
                double a = (k == 0) ? 1.0 : 2.0;
                int m = (2 * k * t) & 127;           // phase units of pi/64
                v = (float)(a * cos(M_PI * (double)m / 64.0));
            } else {
                int m = ((2 * k + 1) * t) & 127;
                v = (float)(2.0 * cos(M_PI * (double)m / 64.0));
            }
        } else if (q == 32) {
            int m4 = t & 3;                          // 2*cos(pi*t/2)
            v = (m4 == 0) ? 2.0f : (m4 == 2) ? -2.0f : 0.0f;
        }
        g_Cf[idx] = v;
    }
}

__global__ __launch_bounds__(256, 4) void subband_kernel(
    const float* __restrict__ inp,   // [B, 1, T, FQ]
    const float* __restrict__ filt,  // [384]
    float* __restrict__ out)         // [B, 1, TRUE_LEN*64]
{
    __shared__ __align__(16) float Ys[ROWS_PAD * YS_STRIDE];       // (E,O) pairs per row
    __shared__ __align__(16) float sXF[2 * ROWS_PAD * XF_STRIDE];  // folded, both parities
    __shared__ __align__(16) float sC[33 * CS];
    __shared__ float sXC[ROWS_PAD];                                // Xe[16] = X[freq 32]
    __shared__ float sF[6 * 64];

    const int tid  = threadIdx.x;
    const int b    = blockIdx.y;
    const int base = blockIdx.x * TILE_H;

    // ---- Phase 1: stage tables + filter; fold spectrum DIRECTLY from gmem ----
    for (int i = tid; i < 33 * CS; i += 256) sC[i] = g_Cf[i];
    if (tid < 128) {
        sF[tid]       = filt[tid];
        sF[tid + 128] = filt[tid + 128];
        sF[tid + 256] = filt[tid + 256];
    }
    int nrows = T_DIM - base; if (nrows > ROWS) nrows = ROWS;
    const float* src = inp + ((size_t)b * T_DIM + base) * FQ;

    // parity folding: each input element read exactly once, coalesced per row
    #pragma unroll
    for (int it = 0; it < 5; it++) {
        int item = tid + it * 256;
        if (item < ROWS_PAD * 16) {
            int r = item >> 4, k = item & 15;
            if (r < nrows) {
                const float* x = src + r * FQ;
                float xeA = x[2 * k],     xeB = x[64 - 2 * k];   // Xe[k], Xe[32-k]
                float xoA = x[2 * k + 1], xoB = x[63 - 2 * k];   // Xo[k], Xo[31-k]
                float* f0 = &sXF[r * XF_STRIDE + 2 * k];
                float* f1 = f0 + ROWS_PAD * XF_STRIDE;
                f0[0] = xeA + xeB;  f0[1] = xoA + xoB;           // even-t fold
                f1[0] = xeA - xeB;  f1[1] = xoA - xoB;           // odd-t fold
                if (k == 0) sXC[r] = x[32];                      // Xe[16] (freq 32)
            }
        }
    }
    __syncthreads();

    // ---- Phase 2: folded cosine transform (packed f32x2: lo=E, hi=O) ----
    // tt in [0,17): t0 = tt, t1 = tt+16 (same parity). rg in [0,14): rows rg*5..rg*5+4.
    if (tid < NTT * NRG) {
        const int tt = tid % NTT;
        const int rg = tid / NTT;
        const int r0 = rg * 5;

        u64 a0q0=0ull,a0q1=0ull,a0q2=0ull,a0q3=0ull,a0q4=0ull;   // t0 accumulators
        u64 a1q0=0ull,a1q1=0ull,a1q2=0ull,a1q3=0ull,a1q4=0ull;   // t1 accumulators

        const u64* cT0 = (const u64*)&sC[tt * CS];
        const u64* cT1 = (const u64*)&sC[(tt + 16) * CS];
        const float* xfb = &sXF[(tt & 1) * (ROWS_PAD * XF_STRIDE) + r0 * XF_STRIDE];

        #pragma unroll
        for (int i2 = 0; i2 < 8; i2++) {                 // 2 k-steps per iter
            u64 cA0 = cT0[2*i2], cB0 = cT0[2*i2+1];
            u64 cA1 = cT1[2*i2], cB1 = cT1[2*i2+1];
            ulonglong2 v0 = ((const ulonglong2*)(xfb + 0 * XF_STRIDE))[i2];
            ulonglong2 v1 = ((const ulonglong2*)(xfb + 1 * XF_STRIDE))[i2];
            ulonglong2 v2 = ((const ulonglong2*)(xfb + 2 * XF_STRIDE))[i2];
            ulonglong2 v3 = ((const ulonglong2*)(xfb + 3 * XF_STRIDE))[i2];
            ulonglong2 v4 = ((const ulonglong2*)(xfb + 4 * XF_STRIDE))[i2];
            FMA_F32X2(a0q0, cA0, v0.x, a0q0);  FMA_F32X2(a0q0, cB0, v0.y, a0q0);
            FMA_F32X2(a1q0, cA1, v0.x, a1q0);  FMA_F32X2(a1q0, cB1, v0.y, a1q0);
            FMA_F32X2(a0q1, cA0, v1.x, a0q1);  FMA_F32X2(a0q1, cB0, v1.y, a0q1);
            FMA_F32X2(a1q1, cA1, v1.x, a1q1);  FMA_F32X2(a1q1, cB1, v1.y, a1q1);
            FMA_F32X2(a0q2, cA0, v2.x, a0q2);  FMA_F32X2(a0q2, cB0, v2.y, a0q2);
            FMA_F32X2(a1q2, cA1, v2.x, a1q2);  FMA_F32X2(a1q2, cB1, v2.y, a1q2);
            FMA_F32X2(a0q3, cA0, v3.x, a0q3);  FMA_F32X2(a0q3, cB0, v3.y, a0q3);
            FMA_F32X2(a1q3, cA1, v3.x, a1q3);  FMA_F32X2(a1q3, cB1, v3.y, a1q3);
            FMA_F32X2(a0q4, cA0, v4.x, a0q4);  FMA_F32X2(a0q4, cB0, v4.y, a0q4);
            FMA_F32X2(a1q4, cA1, v4.x, a1q4);  FMA_F32X2(a1q4, cB1, v4.y, a1q4);
        }

        const float c16a = sC[tt * CS + 32];
        const float c16b = sC[(tt + 16) * CS + 32];
        const int t0 = tt, t1 = tt + 16;

        // store raw (E,O) pairs; phase 3 forms E±O on the fly
        #define SCATTER_Q(qi, A0, A1)                                        \
        {                                                                    \
            float E0, O0, E1, O1;                                            \
            UNPACK_F32X2(E0, O0, A0);                                        \
            UNPACK_F32X2(E1, O1, A1);                                        \
            float xc = sXC[r0 + qi];                                         \
            E0 += c16a * xc;                                                 \
            E1 += c16b * xc;                                                 \
            float2* yr = (float2*)&Ys[(r0 + qi) * YS_STRIDE];                \
            yr[t0] = make_float2(E0, O0);  /* t=16 written twice, same */    \
            yr[t1] = make_float2(E1, O1);  /* values from tt=0 & 16 */       \
        }
        SCATTER_Q(0, a0q0, a1q0)
        SCATTER_Q(1, a0q1, a1q1)
        SCATTER_Q(2, a0q2, a1q2)
        SCATTER_Q(3, a0q3, a1q3)
        SCATTER_Q(4, a0q4, a1q4)
        #undef SCATTER_Q
    }
    __syncthreads();

    // ---- Phase 3: polyphase overlap-add with rolling window ----
    // Y[j] and Y[64-j] both come from pair m = min(j,64-j):  Y = E[m] +/- O[m].
    // out[b,h,j] = (1/512) * (f0*Y[hl+5][j] + f1*Y[hl+4][64-j] + f2*Y[hl+3][j]
    //                        + f3*Y[hl+2][64-j] + f4*Y[hl+1][j] + f5*Y[hl][64-j])
    const int j   = tid & 63;
    const int hg  = tid >> 6;   // 4 h-groups of 16 rows
    const int hl0 = hg * 16;
    const int m   = (j <= 32) ? j : 64 - j;
    const float sB = (j <= 32) ? 1.0f : -1.0f;   // sign for column j
    const float sA = -sB;                         // sign for column 64-j (O[32]=0 -> j=32 safe)
    const float f0 = sF[j],       f1 = sF[64 + j],  f2 = sF[128 + j];
    const float f3 = sF[192 + j], f4 = sF[256 + j], f5 = sF[320 + j];
    float* outb = out + (size_t)b * ((size_t)TRUE_LEN * 64);

    #define YLOAD(row, sg) ({                                                \
        float2 eo = *(const float2*)&Ys[(row) * YS_STRIDE + 2 * m];          \
        eo.x + (sg) * eo.y; })

    #pragma unroll
    for (int p = 0; p < 2; p++) {
        // rows of parity p use column 64-j (sA); parity p^1 use column j (sB)
        int s = hl0 + p;
        float w0 = YLOAD(s + 0, sA);
        float w1 = YLOAD(s + 1, sB);
        float w2 = YLOAD(s + 2, sA);
        float w3 = YLOAD(s + 3, sB);
        float w4 = YLOAD(s + 4, sA);
        float w5 = YLOAD(s + 5, sB);
        #pragma unroll
        for (int q = 0; q < 8; q++) {
            float acc = f5 * w0 + f4 * w1 + f3 * w2 + f2 * w3 + f1 * w4 + f0 * w5;
            int h = base + s;
            if (h < TRUE_LEN) outb[(size_t)h * 64 + j] = acc * (1.0f / 512.0f);
            if (q < 7) {
                w0 = w2; w1 = w3; w2 = w4; w3 = w5;
                w4 = YLOAD(s + 6, sA);
                w5 = YLOAD(s + 7, sB);
                s += 2;
            }
        }
    }
    #undef YLOAD
}

extern "C" void kernel_launch(void* const* d_in, const int* in_sizes, int n_in,
                              void* d_out, int out_size) {
    const float* inp  = (const float*)d_in[0];
    const float* filt = (const float*)d_in[1];
    float* out = (float*)d_out;

    init_tables_kernel<<<5, 256>>>();                   // 33*34 table entries
    dim3 grid((TRUE_LEN + TILE_H - 1) / TILE_H, B_DIM); // 128 x 16
    subband_kernel<<<grid, 256>>>(inp, filt, out);
}

// round 12
// speedup vs baseline: 1.4949x; 1.0154x over previous
#include <cuda_runtime.h>
#include <math.h>

// Problem constants (fixed shapes: B=16, C=1, T=8192, F=65, WINDOW=64)
#define T_DIM     8192
#define B_DIM     16
#define FQ        65          // rfft bins
#define ROWS      69          // input rows per tile (TILE_H + 5 overlap)
#define ROWS_PAD  70          // sXF padded rows (14 rg-groups x 5; row 69 = scratch)
#define TILE_H    64          // output rows per tile
#define TRUE_LEN  (T_DIM - 5) // 8187 output rows per batch
#define NTILES    (128 * B_DIM)
#define GRID_X    608         // 4 blocks/SM x 152 SMs, all resident (persistent)
#define YS_STRIDE 66          // (E,O)-pair row stride in floats (33 float2)
#define XF_STRIDE 36          // folded-X row stride (16B aligned: 144 B)
#define CS        34          // coef row stride (33 values + pad)
#define NTT       17          // t-groups: t in {tt, tt+16}
#define NRG       14          // row-groups of 5 consecutive rows

typedef unsigned long long u64;

// fused dual-FMA: d.lo = a.lo*b.lo + c.lo ; d.hi = a.hi*b.hi + c.hi
#define FMA_F32X2(d, a, b, c) \
    asm("fma.rn.f32x2 %0, %1, %2, %3;" : "=l"(d) : "l"(a), "l"(b), "l"(c))
#define UNPACK_F32X2(lo, hi, in) \
    asm("mov.b64 {%0, %1}, %2;" : "=f"(lo), "=f"(hi) : "l"(in))

// Folded cosine table, row t (t = 0..32), interleaved pairs:
//   g_Cf[t*CS + 2k]   = CEf[t][k] = (k==0 ? 1 : 2) * cos(2*k*t*pi/64),  k=0..15
//   g_Cf[t*CS + 2k+1] = COf[t][k] = 2 * cos((2k+1)*t*pi/64),            k=0..15
//   g_Cf[t*CS + 32]   = c16[t]    = 2 * cos(pi*t/2)  (center term, freq 32)
// Consumed with folded spectra (s = +1 for even t, -1 for odd t):
//   XeF[k] = Xe[k] + s*Xe[32-k], XoF[k] = Xo[k] + s*Xo[31-k]
//   E[t] = sum_k CEf*XeF + c16[t]*Xe[16],  O[t] = sum_k COf*XoF
//   Y[t] = E+O, Y[64-t] = E-O  (irfft of real spectrum, norm='forward')
__device__ float g_Cf[33 * CS];

__global__ void init_tables_kernel() {
    int idx = blockIdx.x * blockDim.x + threadIdx.x;
    if (idx < 33 * CS) {
        int t = idx / CS, q = idx % CS;
        float v = 0.0f;
        if (q < 32) {
            int k = q >> 1;
            if ((q & 1) == 0) {
                double a = (k == 0) ? 1.0 : 2.0;
                int m = (2 * k * t) & 127;           // phase units of pi/64
                v = (float)(a * cos(M_PI * (double)m / 64.0));
            } else {
                int m = ((2 * k + 1) * t) & 127;
                v = (float)(2.0 * cos(M_PI * (double)m / 64.0));
            }
        } else if (q == 32) {
            int m4 = t & 3;                          // 2*cos(pi*t/2)
            v = (m4 == 0) ? 2.0f : (m4 == 2) ? -2.0f : 0.0f;
        }
        g_Cf[idx] = v;
    }
}

__global__ __launch_bounds__(256, 4) void subband_kernel(
    const float* __restrict__ inp,   // [B, 1, T, FQ]
    const float* __restrict__ filt,  // [384]
    float* __restrict__ out)         // [B, 1, TRUE_LEN*64]
{
    __shared__ __align__(16) float Ys[ROWS * YS_STRIDE];           // (E,O) pairs, rows 0..68
    __shared__ __align__(16) float sXF[2 * ROWS_PAD * XF_STRIDE];  // folded, both parities
    __shared__ __align__(16) float sC[33 * CS];
    __shared__ float sXC[ROWS_PAD];                                // Xe[16] = X[freq 32]
    __shared__ float sF[6 * 64];

    const int tid = threadIdx.x;

    // ---- One-time staging (persistent block) ----
    for (int i = tid; i < 33 * CS; i += 256) sC[i] = g_Cf[i];
    if (tid < 128) {
        sF[tid]       = filt[tid];
        sF[tid + 128] = filt[tid + 128];
        sF[tid + 256] = filt[tid + 256];
    }

    // fold lambda: parity folding of tile tg's spectrum directly from gmem
    auto fold = [&](int tg) {
        int fb    = tg >> 7;
        int fbase = (tg & 127) * TILE_H;
        int nrows = T_DIM - fbase; if (nrows > ROWS) nrows = ROWS;
        const float* src = inp + ((size_t)fb * T_DIM + fbase) * FQ;
        #pragma unroll
        for (int it = 0; it < 5; it++) {
            int item = tid + it * 256;
            if (item < ROWS * 16) {
                int r = item >> 4, k = item & 15;
                if (r < nrows) {
                    const float* x = src + r * FQ;
                    float xeA = x[2 * k],     xeB = x[64 - 2 * k];   // Xe[k], Xe[32-k]
                    float xoA = x[2 * k + 1], xoB = x[63 - 2 * k];   // Xo[k], Xo[31-k]
                    float* f0 = &sXF[r * XF_STRIDE + 2 * k];
                    float* f1 = f0 + ROWS_PAD * XF_STRIDE;
                    f0[0] = xeA + xeB;  f0[1] = xoA + xoB;           // even-t fold
                    f1[0] = xeA - xeB;  f1[1] = xoA - xoB;           // odd-t fold
                    if (k == 0) sXC[r] = x[32];                      // Xe[16]
                }
            }
        }
    };

    int tg = blockIdx.x;
    if (tg < NTILES) fold(tg);   // prologue

    for (; tg < NTILES; tg += GRID_X) {
        __syncthreads();   // fold(tg) visible; previous phase3 done with Ys

        // ---- Phase 2: folded cosine transform (packed f32x2: lo=E, hi=O) ----
        // tt in [0,17): t0 = tt, t1 = tt+16 (same parity). rg in [0,14): rows rg*5..rg*5+4.
        if (tid < NTT * NRG) {
            const int tt = tid % NTT;
            const int rg = tid / NTT;
            const int r0 = rg * 5;

            u64 a0q0=0ull,a0q1=0ull,a0q2=0ull,a0q3=0ull,a0q4=0ull;   // t0 accumulators
            u64 a1q0=0ull,a1q1=0ull,a1q2=0ull,a1q3=0ull,a1q4=0ull;   // t1 accumulators

            const u64* cT0 = (const u64*)&sC[tt * CS];
            const u64* cT1 = (const u64*)&sC[(tt + 16) * CS];
            const float* xfb = &sXF[(tt & 1) * (ROWS_PAD * XF_STRIDE) + r0 * XF_STRIDE];

            #pragma unroll
            for (int i2 = 0; i2 < 8; i2++) {                 // 2 k-steps per iter
                u64 cA0 = cT0[2*i2], cB0 = cT0[2*i2+1];
                u64 cA1 = cT1[2*i2], cB1 = cT1[2*i2+1];
                ulonglong2 v0 = ((const ulonglong2*)(xfb + 0 * XF_STRIDE))[i2];
                ulonglong2 v1 = ((const ulonglong2*)(xfb + 1 * XF_STRIDE))[i2];
                ulonglong2 v2 = ((const ulonglong2*)(xfb + 2 * XF_STRIDE))[i2];
                ulonglong2 v3 = ((const ulonglong2*)(xfb + 3 * XF_STRIDE))[i2];
                ulonglong2 v4 = ((const ulonglong2*)(xfb + 4 * XF_STRIDE))[i2];
                FMA_F32X2(a0q0, cA0, v0.x, a0q0);  FMA_F32X2(a0q0, cB0, v0.y, a0q0);
                FMA_F32X2(a1q0, cA1, v0.x, a1q0);  FMA_F32X2(a1q0, cB1, v0.y, a1q0);
                FMA_F32X2(a0q1, cA0, v1.x, a0q1);  FMA_F32X2(a0q1, cB0, v1.y, a0q1);
                FMA_F32X2(a1q1, cA1, v1.x, a1q1);  FMA_F32X2(a1q1, cB1, v1.y, a1q1);
                FMA_F32X2(a0q2, cA0, v2.x, a0q2);  FMA_F32X2(a0q2, cB0, v2.y, a0q2);
                FMA_F32X2(a1q2, cA1, v2.x, a1q2);  FMA_F32X2(a1q2, cB1, v2.y, a1q2);
                FMA_F32X2(a0q3, cA0, v3.x, a0q3);  FMA_F32X2(a0q3, cB0, v3.y, a0q3);
                FMA_F32X2(a1q3, cA1, v3.x, a1q3);  FMA_F32X2(a1q3, cB1, v3.y, a1q3);
                FMA_F32X2(a0q4, cA0, v4.x, a0q4);  FMA_F32X2(a0q4, cB0, v4.y, a0q4);
                FMA_F32X2(a1q4, cA1, v4.x, a1q4);  FMA_F32X2(a1q4, cB1, v4.y, a1q4);
            }

            const float c16a = sC[tt * CS + 32];
            const float c16b = sC[(tt + 16) * CS + 32];
            const int t0 = tt, t1 = tt + 16;

            // store raw (E,O) pairs; phase 3 forms E±O on the fly.
            // guard: rg=13,qi=4 would be row 69 (doesn't exist in Ys)
            #define SCATTER_Q(qi, A0, A1)                                        \
            if (r0 + qi < ROWS) {                                                \
                float E0, O0, E1, O1;                                            \
                UNPACK_F32X2(E0, O0, A0);                                        \
                UNPACK_F32X2(E1, O1, A1);                                        \
                float xc = sXC[r0 + qi];                                         \
                E0 += c16a * xc;                                                 \
                E1 += c16b * xc;                                                 \
                float2* yr = (float2*)&Ys[(r0 + qi) * YS_STRIDE];                \
                yr[t0] = make_float2(E0, O0);  /* t=16 written twice, same */    \
                yr[t1] = make_float2(E1, O1);  /* values from tt=0 & 16 */       \
            }
            SCATTER_Q(0, a0q0, a1q0)
            SCATTER_Q(1, a0q1, a1q1)
            SCATTER_Q(2, a0q2, a1q2)
            SCATTER_Q(3, a0q3, a1q3)
            SCATTER_Q(4, a0q4, a1q4)
            #undef SCATTER_Q
        }
        __syncthreads();   // Ys visible; sXF free for next fold

        // ---- Pipelined fold of NEXT tile (overlaps phase-3 compute) ----
        int tgn = tg + GRID_X;
        if (tgn < NTILES) fold(tgn);

        // ---- Phase 3: polyphase overlap-add with rolling window ----
        // Y[j] and Y[64-j] both come from pair m = min(j,64-j): Y = E[m] +/- O[m].
        // out[b,h,j] = (1/512)*(f0*Y[hl+5][j] + f1*Y[hl+4][64-j] + f2*Y[hl+3][j]
        //                      + f3*Y[hl+2][64-j] + f4*Y[hl+1][j] + f5*Y[hl][64-j])
        {
            const int b    = tg >> 7;
            const int base = (tg & 127) * TILE_H;
            const int j    = tid & 63;
            const int hg   = tid >> 6;   // 4 h-groups of 16 rows
            const int hl0  = hg * 16;
            const int m    = (j <= 32) ? j : 64 - j;
            const float sB = (j <= 32) ? 1.0f : -1.0f;   // sign for column j
            const float sA = -sB;                         // column 64-j (O[32]=0 -> j=32 safe)
            const float f0 = sF[j],       f1 = sF[64 + j],  f2 = sF[128 + j];
            const float f3 = sF[192 + j], f4 = sF[256 + j], f5 = sF[320 + j];
            float* outb = out + (size_t)b * ((size_t)TRUE_LEN * 64);

            #define YLOAD(row, sg) ({                                            \
                float2 eo = *(const float2*)&Ys[(row) * YS_STRIDE + 2 * m];      \
                eo.x + (sg) * eo.y; })

            #pragma unroll
            for (int p = 0; p < 2; p++) {
                int s = hl0 + p;
                float w0 = YLOAD(s + 0, sA);
                float w1 = YLOAD(s + 1, sB);
                float w2 = YLOAD(s + 2, sA);
                float w3 = YLOAD(s + 3, sB);
                float w4 = YLOAD(s + 4, sA);
                float w5 = YLOAD(s + 5, sB);
                #pragma unroll
                for (int q = 0; q < 8; q++) {
                    float acc = f5 * w0 + f4 * w1 + f3 * w2 + f2 * w3 + f1 * w4 + f0 * w5;
                    int h = base + s;
                    if (h < TRUE_LEN) outb[(size_t)h * 64 + j] = acc * (1.0f / 512.0f);
                    if (q < 7) {
                        w0 = w2; w1 = w3; w2 = w4; w3 = w5;
                        w4 = YLOAD(s + 6, sA);
                        w5 = YLOAD(s + 7, sB);
                        s += 2;
                    }
                }
            }
            #undef YLOAD
        }
    }
}

extern "C" void kernel_launch(void* const* d_in, const int* in_sizes, int n_in,
                              void* d_out, int out_size) {
    const float* inp  = (const float*)d_in[0];
    const float* filt = (const float*)d_in[1];
    float* out = (float*)d_out;

    init_tables_kernel<<<5, 256>>>();        // 33*34 table entries
    subband_kernel<<<GRID_X, 256>>>(inp, filt, out);
}